// round 16
// baseline (speedup 1.0000x reference)
#include <cuda_runtime.h>
#include <cstdint>
#include <cstddef>

// Problem dims
#define Hd    512
#define Bn    64
#define OBSn  256
#define FUTn  256
#define Tn    512
#define G4    2048
#define BT    32768
#define BF    16384
#define OUT1  16777216

// ---------------- scratch --------------------------------------------------
__device__ float d_XG[(size_t)BF * G4];
__device__ float d_LH[(size_t)BT * Hd];
__device__ float d_A1[(size_t)BT * Hd];
__device__ float d_A2[(size_t)BT * Hd];
__device__ float d_Qb[(size_t)BT * Hd];
__device__ float d_Kb[(size_t)BT * Hd];
__device__ float d_Vb[(size_t)BT * Hd];
__device__ float d_Hbuf[2][(size_t)Bn * Hd];

// two-level grid barrier state
__device__ unsigned g_bar_grp[8] = {0, 0, 0, 0, 0, 0, 0, 0};
__device__ unsigned g_bar_root = 0;
__device__ volatile unsigned g_bar_gen = 0;

__device__ __forceinline__ float sigmoidf_(float x) { return 1.0f / (1.0f + expf(-x)); }

// ---------------- mma.sync tf32 (raw fp32 bits; tf32 unit truncates) --------
__device__ __forceinline__ void mma_tf32(float* c, const uint32_t* a, const uint32_t* b) {
    asm volatile(
        "mma.sync.aligned.m16n8k8.row.col.f32.tf32.tf32.f32 "
        "{%0,%1,%2,%3}, {%4,%5,%6,%7}, {%8,%9}, {%0,%1,%2,%3};"
        : "+f"(c[0]), "+f"(c[1]), "+f"(c[2]), "+f"(c[3])
        : "r"(a[0]), "r"(a[1]), "r"(a[2]), "r"(a[3]), "r"(b[0]), "r"(b[1]));
}

#define GSTRIDE 1032
#define STAGEW  (2 * GSTRIDE)

__device__ __forceinline__ void sts_perm(
    uint32_t* base, int gidx, int lr, float4 v0, float4 v1)
{
    uint32_t* d = base + gidx * GSTRIDE + lr * 8;
    uint4 w0, w1;
    w0.x = __float_as_uint(v0.x); w0.y = __float_as_uint(v1.x);
    w0.z = __float_as_uint(v0.y); w0.w = __float_as_uint(v1.y);
    w1.x = __float_as_uint(v0.z); w1.y = __float_as_uint(v1.z);
    w1.z = __float_as_uint(v0.w); w1.w = __float_as_uint(v1.w);
    *(uint4*)(d)     = w0;
    *(uint4*)(d + 4) = w1;
}

#define MMA_STAGE_P(Asrc, Wsrc, cacc)                                         \
    _Pragma("unroll")                                                         \
    for (int s_ = 0; s_ < 2; s_++) {                                          \
        const uint32_t* Ag_ = (Asrc) + s_ * GSTRIDE;                          \
        const uint32_t* Wg_ = (Wsrc) + s_ * GSTRIDE;                          \
        uint32_t af_[4][4], bf_[4][2];                                        \
        _Pragma("unroll")                                                     \
        for (int mt_ = 0; mt_ < 4; mt_++) {                                   \
            int mr_ = wm + mt_ * 16 + g;                                      \
            uint2 u0_ = *(const uint2*)&Ag_[mr_ * 8 + 2 * q];                 \
            uint2 u1_ = *(const uint2*)&Ag_[(mr_ + 8) * 8 + 2 * q];           \
            af_[mt_][0] = u0_.x; af_[mt_][1] = u1_.x;                         \
            af_[mt_][2] = u0_.y; af_[mt_][3] = u1_.y;                         \
        }                                                                     \
        _Pragma("unroll")                                                     \
        for (int nt_ = 0; nt_ < 4; nt_++) {                                   \
            int nc_ = wn + nt_ * 8 + g;                                       \
            uint2 u_ = *(const uint2*)&Wg_[nc_ * 8 + 2 * q];                  \
            bf_[nt_][0] = u_.x; bf_[nt_][1] = u_.y;                           \
        }                                                                     \
        _Pragma("unroll")                                                     \
        for (int mt_ = 0; mt_ < 4; mt_++)                                     \
            _Pragma("unroll")                                                 \
            for (int nt_ = 0; nt_ < 4; nt_++)                                 \
                mma_tf32((cacc)[mt_][nt_], af_[mt_], bf_[nt_]);               \
    }

#define SST 136
#define MMA_STAGE_AV(Asrc, Wsrc, cacc)                                        \
    _Pragma("unroll")                                                         \
    for (int s_ = 0; s_ < 2; s_++) {                                          \
        const uint32_t* Ag_ = (Asrc) + s_ * GSTRIDE;                          \
        const int kb_ = s_ * 8;                                               \
        uint32_t af_[4][4], bf_[4][2];                                        \
        _Pragma("unroll")                                                     \
        for (int mt_ = 0; mt_ < 4; mt_++) {                                   \
            int mr_ = wm + mt_ * 16 + g;                                      \
            uint2 u0_ = *(const uint2*)&Ag_[mr_ * 8 + 2 * q];                 \
            uint2 u1_ = *(const uint2*)&Ag_[(mr_ + 8) * 8 + 2 * q];           \
            af_[mt_][0] = u0_.x; af_[mt_][1] = u1_.x;                         \
            af_[mt_][2] = u0_.y; af_[mt_][3] = u1_.y;                         \
        }                                                                     \
        _Pragma("unroll")                                                     \
        for (int nt_ = 0; nt_ < 4; nt_++) {                                   \
            int nc_ = wn + nt_ * 8 + g;                                       \
            bf_[nt_][0] = (Wsrc)[(kb_ + q) * SST + nc_];                      \
            bf_[nt_][1] = (Wsrc)[(kb_ + q + 4) * SST + nc_];                  \
        }                                                                     \
        _Pragma("unroll")                                                     \
        for (int mt_ = 0; mt_ < 4; mt_++)                                     \
            _Pragma("unroll")                                                 \
            for (int nt_ = 0; nt_ < 4; nt_++)                                 \
                mma_tf32((cacc)[mt_][nt_], af_[mt_], bf_[nt_]);               \
    }

// =========== tf32 mma TN GEMM: 256 thr, 8 warps, 64x32 tiles =================
__global__ __launch_bounds__(256) void gemm_mma(
    const float* __restrict__ A, const float* __restrict__ W,
    const float* __restrict__ b1, const float* __restrict__ b2,
    float* __restrict__ C, int M, int N, int K)
{
    __shared__ uint32_t As[2][STAGEW];
    __shared__ uint32_t Ws[2][STAGEW];
    __shared__ float bias_s[128];

    const int t = threadIdx.x, wid = t >> 5, lane = t & 31;
    const int m0 = blockIdx.y * 128, n0 = blockIdx.x * 128;
    const int wm = (wid >> 2) * 64, wn = (wid & 3) * 32;
    const int g = lane >> 2, q = lane & 3;

    if (t < 128) {
        float v = b1 ? b1[n0 + t] : 0.0f;
        if (b2) v += b2[n0 + t];
        bias_s[t] = v;
    }

    float c[4][4][4];
#pragma unroll
    for (int mt = 0; mt < 4; mt++)
#pragma unroll
        for (int nt = 0; nt < 4; nt++)
#pragma unroll
            for (int i = 0; i < 4; i++) c[mt][nt][i] = 0.0f;

    const int lr = t >> 1, gx = t & 1, lk = gx * 8;
    const float* Ap = A + (size_t)(m0 + lr) * K + lk;
    const float* Wp = W + (size_t)(n0 + lr) * K + lk;

    sts_perm(As[0], gx, lr, *(const float4*)Ap, *(const float4*)(Ap + 4));
    sts_perm(Ws[0], gx, lr, *(const float4*)Wp, *(const float4*)(Wp + 4));
    __syncthreads();

    int st = 0;
    for (int k0 = 0; k0 < K; k0 += 16) {
        float4 na0, na1, nw0, nw1;
        const bool more = (k0 + 16) < K;
        if (more) {
            na0 = *(const float4*)(Ap + k0 + 16);
            na1 = *(const float4*)(Ap + k0 + 20);
            nw0 = *(const float4*)(Wp + k0 + 16);
            nw1 = *(const float4*)(Wp + k0 + 20);
        }
        MMA_STAGE_P(As[st], Ws[st], c);
        if (more) {
            int ns = st ^ 1;
            sts_perm(As[ns], gx, lr, na0, na1);
            sts_perm(Ws[ns], gx, lr, nw0, nw1);
            __syncthreads();
            st = ns;
        }
    }

#pragma unroll
    for (int mt = 0; mt < 4; mt++) {
        int mrow = m0 + wm + mt * 16 + g;
#pragma unroll
        for (int nt = 0; nt < 4; nt++) {
            int ncol = wn + nt * 8 + 2 * q;
            float b0v = bias_s[ncol], b1v = bias_s[ncol + 1];
            float2 o0 = make_float2(c[mt][nt][0] + b0v, c[mt][nt][1] + b1v);
            float2 o1 = make_float2(c[mt][nt][2] + b0v, c[mt][nt][3] + b1v);
            *(float2*)&C[(size_t)mrow * N + n0 + ncol]       = o0;
            *(float2*)&C[(size_t)(mrow + 8) * N + n0 + ncol] = o1;
        }
    }
}

// ====== mma scores: causal, masked tiles skipped ==============================
__global__ __launch_bounds__(256) void gemm_mma_scores(
    const float* __restrict__ Qm, const float* __restrict__ Km,
    float* __restrict__ C, float scale)
{
    __shared__ uint32_t As[2][STAGEW];
    __shared__ uint32_t Ws[2][STAGEW];
    const size_t bo = (size_t)blockIdx.z * 262144;
    const int m0 = blockIdx.y * 128, n0 = blockIdx.x * 128;
    float* Cb = C + bo;
    const int t = threadIdx.x;

    if (n0 > m0 + 127) return;

    const int wid = t >> 5, lane = t & 31;
    const int wm = (wid >> 2) * 64, wn = (wid & 3) * 32;
    const int g = lane >> 2, q = lane & 3;

    float c[4][4][4];
#pragma unroll
    for (int mt = 0; mt < 4; mt++)
#pragma unroll
        for (int nt = 0; nt < 4; nt++)
#pragma unroll
            for (int i = 0; i < 4; i++) c[mt][nt][i] = 0.0f;

    const int lr = t >> 1, gx = t & 1, lk = gx * 8;
    const float* Ap = Qm + bo + (size_t)(m0 + lr) * 512 + lk;
    const float* Wp = Km + bo + (size_t)(n0 + lr) * 512 + lk;

    sts_perm(As[0], gx, lr, *(const float4*)Ap, *(const float4*)(Ap + 4));
    sts_perm(Ws[0], gx, lr, *(const float4*)Wp, *(const float4*)(Wp + 4));
    __syncthreads();

    int st = 0;
    for (int k0 = 0; k0 < 512; k0 += 16) {
        float4 na0, na1, nw0, nw1;
        const bool more = (k0 + 16) < 512;
        if (more) {
            na0 = *(const float4*)(Ap + k0 + 16);
            na1 = *(const float4*)(Ap + k0 + 20);
            nw0 = *(const float4*)(Wp + k0 + 16);
            nw1 = *(const float4*)(Wp + k0 + 20);
        }
        MMA_STAGE_P(As[st], Ws[st], c);
        if (more) {
            int ns = st ^ 1;
            sts_perm(As[ns], gx, lr, na0, na1);
            sts_perm(Ws[ns], gx, lr, nw0, nw1);
            __syncthreads();
            st = ns;
        }
    }

#pragma unroll
    for (int mt = 0; mt < 4; mt++) {
        int q0 = m0 + wm + mt * 16 + g;
        int q1 = q0 + 8;
#pragma unroll
        for (int nt = 0; nt < 4; nt++) {
            int kk = n0 + wn + nt * 8 + 2 * q;
            float2 o0, o1;
            o0.x = (kk     > q0) ? -1e30f : c[mt][nt][0] * scale;
            o0.y = (kk + 1 > q0) ? -1e30f : c[mt][nt][1] * scale;
            o1.x = (kk     > q1) ? -1e30f : c[mt][nt][2] * scale;
            o1.y = (kk + 1 > q1) ? -1e30f : c[mt][nt][3] * scale;
            *(float2*)&Cb[(size_t)q0 * 512 + kk] = o0;
            *(float2*)&Cb[(size_t)q1 * 512 + kk] = o1;
        }
    }
}

// ====== mma AV: O = attn @ V, K truncated (exact) =============================
__global__ __launch_bounds__(256) void gemm_mma_av(
    const float* __restrict__ Am, const float* __restrict__ Bm, float* __restrict__ C)
{
    __shared__ uint32_t As[2][STAGEW];
    __shared__ uint32_t Vs[2][16 * SST];
    const size_t bo = (size_t)blockIdx.z * 262144;
    const float* B = Bm + bo;
    float* Cb = C + bo;
    const int m0 = blockIdx.y * 128, n0 = blockIdx.x * 128;
    const int Kmax = m0 + 128;
    const int t = threadIdx.x, wid = t >> 5, lane = t & 31;
    const int wm = (wid >> 2) * 64, wn = (wid & 3) * 32;
    const int g = lane >> 2, q = lane & 3;

    float c[4][4][4];
#pragma unroll
    for (int mt = 0; mt < 4; mt++)
#pragma unroll
        for (int nt = 0; nt < 4; nt++)
#pragma unroll
            for (int i = 0; i < 4; i++) c[mt][nt][i] = 0.0f;

    const int lr = t >> 1, gx = t & 1, lk = gx * 8;
    const float* Ap = Am + bo + (size_t)(m0 + lr) * 512 + lk;
    const int vkr = t >> 4, vnc = (t & 15) * 8;
    const float* Vp = B + (size_t)vkr * 512 + n0 + vnc;

    {
        sts_perm(As[0], gx, lr, *(const float4*)Ap, *(const float4*)(Ap + 4));
        float4 v0 = *(const float4*)(Vp);
        float4 v1 = *(const float4*)(Vp + 4);
        uint32_t* d = &Vs[0][vkr * SST + vnc];
        d[0] = __float_as_uint(v0.x); d[1] = __float_as_uint(v0.y);
        d[2] = __float_as_uint(v0.z); d[3] = __float_as_uint(v0.w);
        d[4] = __float_as_uint(v1.x); d[5] = __float_as_uint(v1.y);
        d[6] = __float_as_uint(v1.z); d[7] = __float_as_uint(v1.w);
    }
    __syncthreads();

    int st = 0;
    for (int k0 = 0; k0 < Kmax; k0 += 16) {
        float4 na0, na1, nv0, nv1;
        const bool more = (k0 + 16) < Kmax;
        if (more) {
            na0 = *(const float4*)(Ap + k0 + 16);
            na1 = *(const float4*)(Ap + k0 + 20);
            nv0 = *(const float4*)(Vp + (size_t)(k0 + 16) * 512);
            nv1 = *(const float4*)(Vp + (size_t)(k0 + 16) * 512 + 4);
        }
        MMA_STAGE_AV(As[st], Vs[st], c);
        if (more) {
            int ns = st ^ 1;
            sts_perm(As[ns], gx, lr, na0, na1);
            uint32_t* d = &Vs[ns][vkr * SST + vnc];
            d[0] = __float_as_uint(nv0.x); d[1] = __float_as_uint(nv0.y);
            d[2] = __float_as_uint(nv0.z); d[3] = __float_as_uint(nv0.w);
            d[4] = __float_as_uint(nv1.x); d[5] = __float_as_uint(nv1.y);
            d[6] = __float_as_uint(nv1.z); d[7] = __float_as_uint(nv1.w);
            __syncthreads();
            st = ns;
        }
    }

#pragma unroll
    for (int mt = 0; mt < 4; mt++) {
        int mrow = m0 + wm + mt * 16 + g;
#pragma unroll
        for (int nt = 0; nt < 4; nt++) {
            int ncol = wn + nt * 8 + 2 * q;
            float2 o0 = make_float2(c[mt][nt][0], c[mt][nt][1]);
            float2 o1 = make_float2(c[mt][nt][2], c[mt][nt][3]);
            *(float2*)&Cb[(size_t)mrow * 512 + n0 + ncol]       = o0;
            *(float2*)&Cb[(size_t)(mrow + 8) * 512 + n0 + ncol] = o1;
        }
    }
}

// ======================= copy observed rows into lstm_hidden ==================
__global__ void copy_obs_k(const float* __restrict__ obs, float* __restrict__ LH)
{
    size_t i = (size_t)blockIdx.x * blockDim.x + threadIdx.x;
    if (i < (size_t)Bn * OBSn * Hd) {
        size_t b = i >> 17;
        size_t rem = i & 131071;
        LH[b * 262144 + rem] = obs[i];
    }
}

// ============ persistent LSTM v9: tensor-core gate GEMM =======================
// Block owns 4 units (16 gate rows). Per step: gates[64b x 16r] =
// h[64 x 512] @ W[16 x 512]^T via m16n8k8 tf32 mma (A from Hs[k][batch] stride
// 72: bank 8q+g distinct; B from Ws[row][k] stride 520: bank 8g+q distinct).
// 8 warps = 4 batch-tiles x 2 row-tiles. Cell state fp32 in registers.
#define HTS 72
#define WTS 520
#define GP2 66
__global__ __launch_bounds__(256, 1) void lstm_persist(
    const float* __restrict__ obs, const float* __restrict__ XG,
    const float* __restrict__ Whh, float* __restrict__ LH,
    float* __restrict__ Hb)
{
    extern __shared__ float sh[];
    float* Hs = sh;                        // [512][HTS]  (k, batch)
    float* Ws = sh + 512 * HTS;            // [16][WTS]
    __shared__ float gsm[16 * GP2];        // [row][batch]

    const int t = threadIdx.x;
    const int ublk = blockIdx.x * 4;
    const int grp = blockIdx.x >> 4;

    // load W rows (local row r = gate*4 + unit)
    for (int idx = t; idx < 16 * 128; idx += 256) {
        int row = idx >> 7, qq = idx & 127;
        int g = row >> 2, j = row & 3;
        float4 v = *(const float4*)(Whh + (size_t)(g * 512 + ublk + j) * 512 + qq * 4);
        *(float4*)(Ws + row * WTS + qq * 4) = v;
    }

    const int wid = t >> 5, lane = t & 31;
    const int mt = wid & 3, nt = wid >> 2;    // batch tile, row tile
    const int g = lane >> 2, q = lane & 3;
    const int mb = mt * 16;

    const int pb = t >> 2, pj = t & 3;
    float c_reg = obs[(size_t)pb * 131072 + 255 * 512 + ublk + pj];

    // copy role: thread -> (batch lm, k quarter q4); writes transposed
    const int lm = t & 63, q4 = t >> 6;

    for (int s = 0; s < 256; s++) {
        const float* xrow = XG + (size_t)(pb * 256 + s) * 2048 + ublk + pj;
        float xg0 = __ldcg(xrow);
        float xg1 = __ldcg(xrow + 512);
        float xg2 = __ldcg(xrow + 1024);
        float xg3 = __ldcg(xrow + 1536);

        // load h_prev and store TRANSPOSED into Hs[k][batch]
        {
            const float* hsrc; size_t hstr;
            if (s == 0) { hsrc = obs + 255 * 512; hstr = 131072; }
            else        { hsrc = Hb + (size_t)(s & 1) * (Bn * Hd); hstr = 512; }
            const float* src = hsrc + (size_t)lm * hstr + q4 * 128;
#pragma unroll
            for (int i = 0; i < 32; i++) {
                float4 v = __ldcg((const float4*)(src + i * 4));
                int kk = q4 * 128 + i * 4;
                Hs[(kk + 0) * HTS + lm] = v.x;
                Hs[(kk + 1) * HTS + lm] = v.y;
                Hs[(kk + 2) * HTS + lm] = v.z;
                Hs[(kk + 3) * HTS + lm] = v.w;
            }
        }
        __syncthreads();

        // tensor-core gate GEMM: warp (mt, nt) -> batches mb..+15, rows nt*8..+7
        {
            float c0 = 0.f, c1 = 0.f, c2 = 0.f, c3 = 0.f;
            const float* wrow = Ws + (nt * 8 + g) * WTS;
#pragma unroll 8
            for (int ks = 0; ks < 64; ks++) {
                int k0 = ks * 8;
                uint32_t a[4], b[2];
                a[0] = __float_as_uint(Hs[(k0 + q) * HTS + mb + g]);
                a[1] = __float_as_uint(Hs[(k0 + q) * HTS + mb + g + 8]);
                a[2] = __float_as_uint(Hs[(k0 + q + 4) * HTS + mb + g]);
                a[3] = __float_as_uint(Hs[(k0 + q + 4) * HTS + mb + g + 8]);
                b[0] = __float_as_uint(wrow[k0 + q]);
                b[1] = __float_as_uint(wrow[k0 + q + 4]);
                float cc[4] = {c0, c1, c2, c3};
                mma_tf32(cc, a, b);
                c0 = cc[0]; c1 = cc[1]; c2 = cc[2]; c3 = cc[3];
            }
            // c0: (batch mb+g, row nt*8+2q), c1: row+1; c2/c3: batch mb+g+8
            gsm[(nt * 8 + 2 * q) * GP2 + mb + g]         = c0;
            gsm[(nt * 8 + 2 * q + 1) * GP2 + mb + g]     = c1;
            gsm[(nt * 8 + 2 * q) * GP2 + mb + g + 8]     = c2;
            gsm[(nt * 8 + 2 * q + 1) * GP2 + mb + g + 8] = c3;
        }
        __syncthreads();

        // pointwise gate math + dual h store
        {
            float gi = gsm[(0 * 4 + pj) * GP2 + pb] + xg0;
            float gf = gsm[(1 * 4 + pj) * GP2 + pb] + xg1;
            float gg = gsm[(2 * 4 + pj) * GP2 + pb] + xg2;
            float go = gsm[(3 * 4 + pj) * GP2 + pb] + xg3;
            c_reg = sigmoidf_(gf) * c_reg + sigmoidf_(gi) * tanhf(gg);
            float hv = sigmoidf_(go) * tanhf(c_reg);
            LH[(size_t)pb * 262144 + (size_t)(256 + s) * 512 + ublk + pj] = hv;
            Hb[(size_t)((s + 1) & 1) * (Bn * Hd) + (size_t)pb * 512 + ublk + pj] = hv;
        }

        // two-level grid barrier
        __threadfence();
        __syncthreads();
        if (t == 0) {
            unsigned snap = g_bar_gen;
            unsigned o = atomicAdd(&g_bar_grp[grp], 1u);
            if (o == 15u) {
                g_bar_grp[grp] = 0;
                __threadfence();
                unsigned r = atomicAdd(&g_bar_root, 1u);
                if (r == 7u) {
                    g_bar_root = 0;
                    __threadfence();
                    g_bar_gen = snap + 1u;
                } else {
                    while (g_bar_gen == snap) __nanosleep(32);
                }
            } else {
                while (g_bar_gen == snap) __nanosleep(32);
            }
            __threadfence();
        }
        __syncthreads();
    }
}

// ====================== fused GLU + LayerNorm =================================
__global__ __launch_bounds__(256) void gluln_k(
    const float* __restrict__ a1, const float* __restrict__ a2,
    const float* __restrict__ y1, const float* __restrict__ y2,
    const float* __restrict__ gamma, const float* __restrict__ beta,
    float* __restrict__ outp, int splitY)
{
    __shared__ float red[8];
    const int r = blockIdx.x;
    const int t = threadIdx.x;
    const float* yp;
    if (splitY) {
        int b = r >> 9, tt = r & 511;
        yp = (tt < 256) ? (y1 + ((size_t)(b * 256 + tt)) * 512)
                        : (y2 + ((size_t)(b * 256 + tt - 256)) * 512);
    } else {
        yp = y1 + (size_t)r * 512;
    }
    const float* p1 = a1 + (size_t)r * 512;
    const float* p2 = a2 + (size_t)r * 512;
    float z0 = sigmoidf_(p1[t])       * p2[t]       + yp[t];
    float z1 = sigmoidf_(p1[t + 256]) * p2[t + 256] + yp[t + 256];

    float s = z0 + z1;
#pragma unroll
    for (int o = 16; o > 0; o >>= 1) s += __shfl_xor_sync(0xffffffffu, s, o);
    if ((t & 31) == 0) red[t >> 5] = s;
    __syncthreads();
    if (t < 32) {
        float a = (t < 8) ? red[t] : 0.0f;
#pragma unroll
        for (int o = 4; o > 0; o >>= 1) a += __shfl_xor_sync(0xffffffffu, a, o);
        if (t == 0) red[0] = a;
    }
    __syncthreads();
    float mu = red[0] * (1.0f / 512.0f);
    float d0 = z0 - mu, d1 = z1 - mu;
    float s2 = d0 * d0 + d1 * d1;
    __syncthreads();
#pragma unroll
    for (int o = 16; o > 0; o >>= 1) s2 += __shfl_xor_sync(0xffffffffu, s2, o);
    if ((t & 31) == 0) red[t >> 5] = s2;
    __syncthreads();
    if (t < 32) {
        float a = (t < 8) ? red[t] : 0.0f;
#pragma unroll
        for (int o = 4; o > 0; o >>= 1) a += __shfl_xor_sync(0xffffffffu, a, o);
        if (t == 0) red[0] = a;
    }
    __syncthreads();
    float inv = rsqrtf(red[0] * (1.0f / 512.0f) + 1e-5f);
    outp[(size_t)r * 512 + t]       = gamma[t]       * d0 * inv + beta[t];
    outp[(size_t)r * 512 + t + 256] = gamma[t + 256] * d1 * inv + beta[t + 256];
}

// ====== mask-aware row softmax ================================================
__global__ __launch_bounds__(256) void softmax_k(
    const float* __restrict__ S, float* __restrict__ A)
{
    __shared__ float red[8];
    const int r = blockIdx.x;
    const int t = threadIdx.x;
    const int qpos = r & 511;
    const float* p = S + (size_t)r * 512;
    float v0 = (t <= qpos)       ? p[t]       : -3.4e38f;
    float v1 = (t + 256 <= qpos) ? p[t + 256] : -3.4e38f;
    float m = fmaxf(v0, v1);
#pragma unroll
    for (int o = 16; o > 0; o >>= 1) m = fmaxf(m, __shfl_xor_sync(0xffffffffu, m, o));
    if ((t & 31) == 0) red[t >> 5] = m;
    __syncthreads();
    if (t < 32) {
        float a = (t < 8) ? red[t] : -3.4e38f;
#pragma unroll
        for (int o = 4; o > 0; o >>= 1) a = fmaxf(a, __shfl_xor_sync(0xffffffffu, a, o));
        if (t == 0) red[0] = a;
    }
    __syncthreads();
    float mx = red[0];
    float e0 = (t <= qpos)       ? expf(v0 - mx) : 0.0f;
    float e1 = (t + 256 <= qpos) ? expf(v1 - mx) : 0.0f;
    float s = e0 + e1;
    __syncthreads();
#pragma unroll
    for (int o = 16; o > 0; o >>= 1) s += __shfl_xor_sync(0xffffffffu, s, o);
    if ((t & 31) == 0) red[t >> 5] = s;
    __syncthreads();
    if (t < 32) {
        float a = (t < 8) ? red[t] : 0.0f;
#pragma unroll
        for (int o = 4; o > 0; o >>= 1) a += __shfl_xor_sync(0xffffffffu, a, o);
        if (t == 0) red[0] = a;
    }
    __syncthreads();
    float inv = 1.0f / red[0];
    A[(size_t)r * 512 + t]       = e0 * inv;
    A[(size_t)r * 512 + t + 256] = e1 * inv;
}

// ================================= host =======================================
extern "C" void kernel_launch(void* const* d_in, const int* in_sizes, int n_in,
                              void* d_out, int out_size)
{
    const float* obs   = (const float*)d_in[0];
    const float* fut   = (const float*)d_in[1];
    const float* W_ih  = (const float*)d_in[2];
    const float* W_hh  = (const float*)d_in[3];
    const float* b_ih  = (const float*)d_in[4];
    const float* b_hh  = (const float*)d_in[5];
    const float* g1W1  = (const float*)d_in[6];
    const float* g1b1  = (const float*)d_in[7];
    const float* g1W2  = (const float*)d_in[8];
    const float* g1b2  = (const float*)d_in[9];
    const float* g1g   = (const float*)d_in[10];
    const float* g1b   = (const float*)d_in[11];
    const float* Wq    = (const float*)d_in[12];
    const float* bq    = (const float*)d_in[13];
    const float* Wk    = (const float*)d_in[14];
    const float* bk    = (const float*)d_in[15];
    const float* Wv    = (const float*)d_in[16];
    const float* bv    = (const float*)d_in[17];
    const float* Wo    = (const float*)d_in[18];
    const float* bo    = (const float*)d_in[19];
    const float* g2W1  = (const float*)d_in[20];
    const float* g2b1  = (const float*)d_in[21];
    const float* g2W2  = (const float*)d_in[22];
    const float* g2b2  = (const float*)d_in[23];
    const float* g2g   = (const float*)d_in[24];
    const float* g2b   = (const float*)d_in[25];

    float* out       = (float*)d_out;
    float* glu_delta = out;
    float* glu_phi   = out + (size_t)OUT1;
    float* attn      = out + (size_t)2 * OUT1;

    float *XG, *LH, *A1, *A2, *Qb, *Kb, *Vb, *Hb;
    cudaGetSymbolAddress((void**)&XG, d_XG);
    cudaGetSymbolAddress((void**)&LH, d_LH);
    cudaGetSymbolAddress((void**)&A1, d_A1);
    cudaGetSymbolAddress((void**)&A2, d_A2);
    cudaGetSymbolAddress((void**)&Qb, d_Qb);
    cudaGetSymbolAddress((void**)&Kb, d_Kb);
    cudaGetSymbolAddress((void**)&Vb, d_Vb);
    cudaGetSymbolAddress((void**)&Hb, d_Hbuf);

    // 1. X_gates = fut @ W_ih^T + (b_ih + b_hh)
    gemm_mma<<<dim3(G4 / 128, BF / 128), 256>>>(fut, W_ih, b_ih, b_hh, XG, BF, G4, Hd);

    // 2. lstm_hidden[:, :256, :] = vsn_observed
    copy_obs_k<<<(Bn * OBSn * Hd + 255) / 256, 256>>>(obs, LH);

    // 3. persistent LSTM over all 256 steps (tensor-core gates)
    {
        const int smem = (512 * HTS + 16 * WTS) * 4;   // 147456 + 33280 = 180736
        cudaFuncSetAttribute(lstm_persist, cudaFuncAttributeMaxDynamicSharedMemorySize, smem);
        lstm_persist<<<128, 256, smem>>>(obs, XG, W_hh, LH, Hb);
    }

    // 4. GLU-LN #1 -> glu_phi
    gemm_mma<<<dim3(4, 256), 256>>>(LH, g1W1, g1b1, nullptr, A1, BT, Hd, Hd);
    gemm_mma<<<dim3(4, 256), 256>>>(LH, g1W2, g1b2, nullptr, A2, BT, Hd, Hd);
    gluln_k<<<BT, 256>>>(A1, A2, obs, fut, g1g, g1b, glu_phi, 1);

    // 5. QKV
    gemm_mma<<<dim3(4, 256), 256>>>(glu_phi, Wq, bq, nullptr, Qb, BT, Hd, Hd);
    gemm_mma<<<dim3(4, 256), 256>>>(glu_phi, Wk, bk, nullptr, Kb, BT, Hd, Hd);
    gemm_mma<<<dim3(4, 256), 256>>>(glu_phi, Wv, bv, nullptr, Vb, BT, Hd, Hd);

    // 6. scores + mask-aware softmax -> attn
    gemm_mma_scores<<<dim3(4, 4, 64), 256>>>(Qb, Kb, XG, 0.04419417382415922f);
    softmax_k<<<BT, 256>>>(XG, attn);

    // 7. attn @ V -> Qb; projection -> Kb
    gemm_mma_av<<<dim3(4, 4, 64), 256>>>(attn, Vb, Qb);
    gemm_mma<<<dim3(4, 256), 256>>>(Qb, Wo, bo, nullptr, Kb, BT, Hd, Hd);

    // 8. GLU-LN #2 -> glu_delta
    gemm_mma<<<dim3(4, 256), 256>>>(Kb, g2W1, g2b1, nullptr, A1, BT, Hd, Hd);
    gemm_mma<<<dim3(4, 256), 256>>>(Kb, g2W2, g2b2, nullptr, A2, BT, Hd, Hd);
    gluln_k<<<BT, 256>>>(A1, A2, glu_phi, nullptr, g2g, g2b, glu_delta, 0);
}

// round 17
// speedup vs baseline: 1.1583x; 1.1583x over previous
#include <cuda_runtime.h>
#include <cstdint>
#include <cstddef>

// Problem dims
#define Hd    512
#define Bn    64
#define OBSn  256
#define FUTn  256
#define Tn    512
#define G4    2048
#define BT    32768
#define BF    16384
#define OUT1  16777216

// ---------------- scratch --------------------------------------------------
__device__ float d_XG[(size_t)BF * G4];
__device__ float d_LH[(size_t)BT * Hd];
__device__ float d_A1[(size_t)BT * Hd];
__device__ float d_A2[(size_t)BT * Hd];
__device__ float d_Qb[(size_t)BT * Hd];
__device__ float d_Kb[(size_t)BT * Hd];
__device__ float d_Vb[(size_t)BT * Hd];
__device__ float d_Hbuf[2][(size_t)Bn * Hd];

// two-level grid barrier state
__device__ unsigned g_bar_grp[8] = {0, 0, 0, 0, 0, 0, 0, 0};
__device__ unsigned g_bar_root = 0;
__device__ volatile unsigned g_bar_gen = 0;

__device__ __forceinline__ float sigmoidf_(float x) { return 1.0f / (1.0f + expf(-x)); }

// ---------------- packed f32x2 FMA (Blackwell FFMA2) -------------------------
#define FMA2(acc, a, b) \
    asm volatile("fma.rn.f32x2 %0, %1, %2, %0;" : "+l"(acc) : "l"(a), "l"(b))
#define PACK2(dst, lo, hi) \
    asm("mov.b64 %0, {%1, %2};" : "=l"(dst) : "f"(lo), "f"(hi))
#define UNPACK2(lo, hi, src) \
    asm("mov.b64 {%0, %1}, %2;" : "=f"(lo), "=f"(hi) : "l"(src))

// ---------------- mma.sync tf32 (raw fp32 bits) ------------------------------
__device__ __forceinline__ void mma_tf32(float* c, const uint32_t* a, const uint32_t* b) {
    asm volatile(
        "mma.sync.aligned.m16n8k8.row.col.f32.tf32.tf32.f32 "
        "{%0,%1,%2,%3}, {%4,%5,%6,%7}, {%8,%9}, {%0,%1,%2,%3};"
        : "+f"(c[0]), "+f"(c[1]), "+f"(c[2]), "+f"(c[3])
        : "r"(a[0]), "r"(a[1]), "r"(a[2]), "r"(a[3]), "r"(b[0]), "r"(b[1]));
}

#define GSTRIDE 1032
#define STAGEW  (2 * GSTRIDE)

__device__ __forceinline__ void sts_perm(
    uint32_t* base, int gidx, int lr, float4 v0, float4 v1)
{
    uint32_t* d = base + gidx * GSTRIDE + lr * 8;
    uint4 w0, w1;
    w0.x = __float_as_uint(v0.x); w0.y = __float_as_uint(v1.x);
    w0.z = __float_as_uint(v0.y); w0.w = __float_as_uint(v1.y);
    w1.x = __float_as_uint(v0.z); w1.y = __float_as_uint(v1.z);
    w1.z = __float_as_uint(v0.w); w1.w = __float_as_uint(v1.w);
    *(uint4*)(d)     = w0;
    *(uint4*)(d + 4) = w1;
}

#define MMA_STAGE_P(Asrc, Wsrc, cacc)                                         \
    _Pragma("unroll")                                                         \
    for (int s_ = 0; s_ < 2; s_++) {                                          \
        const uint32_t* Ag_ = (Asrc) + s_ * GSTRIDE;                          \
        const uint32_t* Wg_ = (Wsrc) + s_ * GSTRIDE;                          \
        uint32_t af_[4][4], bf_[4][2];                                        \
        _Pragma("unroll")                                                     \
        for (int mt_ = 0; mt_ < 4; mt_++) {                                   \
            int mr_ = wm + mt_ * 16 + g;                                      \
            uint2 u0_ = *(const uint2*)&Ag_[mr_ * 8 + 2 * q];                 \
            uint2 u1_ = *(const uint2*)&Ag_[(mr_ + 8) * 8 + 2 * q];           \
            af_[mt_][0] = u0_.x; af_[mt_][1] = u1_.x;                         \
            af_[mt_][2] = u0_.y; af_[mt_][3] = u1_.y;                         \
        }                                                                     \
        _Pragma("unroll")                                                     \
        for (int nt_ = 0; nt_ < 4; nt_++) {                                   \
            int nc_ = wn + nt_ * 8 + g;                                       \
            uint2 u_ = *(const uint2*)&Wg_[nc_ * 8 + 2 * q];                  \
            bf_[nt_][0] = u_.x; bf_[nt_][1] = u_.y;                           \
        }                                                                     \
        _Pragma("unroll")                                                     \
        for (int mt_ = 0; mt_ < 4; mt_++)                                     \
            _Pragma("unroll")                                                 \
            for (int nt_ = 0; nt_ < 4; nt_++)                                 \
                mma_tf32((cacc)[mt_][nt_], af_[mt_], bf_[nt_]);               \
    }

#define SST 136
#define MMA_STAGE_AV(Asrc, Wsrc, cacc)                                        \
    _Pragma("unroll")                                                         \
    for (int s_ = 0; s_ < 2; s_++) {                                          \
        const uint32_t* Ag_ = (Asrc) + s_ * GSTRIDE;                          \
        const int kb_ = s_ * 8;                                               \
        uint32_t af_[4][4], bf_[4][2];                                        \
        _Pragma("unroll")                                                     \
        for (int mt_ = 0; mt_ < 4; mt_++) {                                   \
            int mr_ = wm + mt_ * 16 + g;                                      \
            uint2 u0_ = *(const uint2*)&Ag_[mr_ * 8 + 2 * q];                 \
            uint2 u1_ = *(const uint2*)&Ag_[(mr_ + 8) * 8 + 2 * q];           \
            af_[mt_][0] = u0_.x; af_[mt_][1] = u1_.x;                         \
            af_[mt_][2] = u0_.y; af_[mt_][3] = u1_.y;                         \
        }                                                                     \
        _Pragma("unroll")                                                     \
        for (int nt_ = 0; nt_ < 4; nt_++) {                                   \
            int nc_ = wn + nt_ * 8 + g;                                       \
            bf_[nt_][0] = (Wsrc)[(kb_ + q) * SST + nc_];                      \
            bf_[nt_][1] = (Wsrc)[(kb_ + q + 4) * SST + nc_];                  \
        }                                                                     \
        _Pragma("unroll")                                                     \
        for (int mt_ = 0; mt_ < 4; mt_++)                                     \
            _Pragma("unroll")                                                 \
            for (int nt_ = 0; nt_ < 4; nt_++)                                 \
                mma_tf32((cacc)[mt_][nt_], af_[mt_], bf_[nt_]);               \
    }

// =========== tf32 mma TN GEMM: 256 thr, 8 warps, 64x32 tiles =================
__global__ __launch_bounds__(256) void gemm_mma(
    const float* __restrict__ A, const float* __restrict__ W,
    const float* __restrict__ b1, const float* __restrict__ b2,
    float* __restrict__ C, int M, int N, int K)
{
    __shared__ uint32_t As[2][STAGEW];
    __shared__ uint32_t Ws[2][STAGEW];
    __shared__ float bias_s[128];

    const int t = threadIdx.x, wid = t >> 5, lane = t & 31;
    const int m0 = blockIdx.y * 128, n0 = blockIdx.x * 128;
    const int wm = (wid >> 2) * 64, wn = (wid & 3) * 32;
    const int g = lane >> 2, q = lane & 3;

    if (t < 128) {
        float v = b1 ? b1[n0 + t] : 0.0f;
        if (b2) v += b2[n0 + t];
        bias_s[t] = v;
    }

    float c[4][4][4];
#pragma unroll
    for (int mt = 0; mt < 4; mt++)
#pragma unroll
        for (int nt = 0; nt < 4; nt++)
#pragma unroll
            for (int i = 0; i < 4; i++) c[mt][nt][i] = 0.0f;

    const int lr = t >> 1, gx = t & 1, lk = gx * 8;
    const float* Ap = A + (size_t)(m0 + lr) * K + lk;
    const float* Wp = W + (size_t)(n0 + lr) * K + lk;

    sts_perm(As[0], gx, lr, *(const float4*)Ap, *(const float4*)(Ap + 4));
    sts_perm(Ws[0], gx, lr, *(const float4*)Wp, *(const float4*)(Wp + 4));
    __syncthreads();

    int st = 0;
    for (int k0 = 0; k0 < K; k0 += 16) {
        float4 na0, na1, nw0, nw1;
        const bool more = (k0 + 16) < K;
        if (more) {
            na0 = *(const float4*)(Ap + k0 + 16);
            na1 = *(const float4*)(Ap + k0 + 20);
            nw0 = *(const float4*)(Wp + k0 + 16);
            nw1 = *(const float4*)(Wp + k0 + 20);
        }
        MMA_STAGE_P(As[st], Ws[st], c);
        if (more) {
            int ns = st ^ 1;
            sts_perm(As[ns], gx, lr, na0, na1);
            sts_perm(Ws[ns], gx, lr, nw0, nw1);
            __syncthreads();
            st = ns;
        }
    }

#pragma unroll
    for (int mt = 0; mt < 4; mt++) {
        int mrow = m0 + wm + mt * 16 + g;
#pragma unroll
        for (int nt = 0; nt < 4; nt++) {
            int ncol = wn + nt * 8 + 2 * q;
            float b0v = bias_s[ncol], b1v = bias_s[ncol + 1];
            float2 o0 = make_float2(c[mt][nt][0] + b0v, c[mt][nt][1] + b1v);
            float2 o1 = make_float2(c[mt][nt][2] + b0v, c[mt][nt][3] + b1v);
            *(float2*)&C[(size_t)mrow * N + n0 + ncol]       = o0;
            *(float2*)&C[(size_t)(mrow + 8) * N + n0 + ncol] = o1;
        }
    }
}

// ====== mma scores: causal, masked tiles skipped ==============================
__global__ __launch_bounds__(256) void gemm_mma_scores(
    const float* __restrict__ Qm, const float* __restrict__ Km,
    float* __restrict__ C, float scale)
{
    __shared__ uint32_t As[2][STAGEW];
    __shared__ uint32_t Ws[2][STAGEW];
    const size_t bo = (size_t)blockIdx.z * 262144;
    const int m0 = blockIdx.y * 128, n0 = blockIdx.x * 128;
    float* Cb = C + bo;
    const int t = threadIdx.x;

    if (n0 > m0 + 127) return;

    const int wid = t >> 5, lane = t & 31;
    const int wm = (wid >> 2) * 64, wn = (wid & 3) * 32;
    const int g = lane >> 2, q = lane & 3;

    float c[4][4][4];
#pragma unroll
    for (int mt = 0; mt < 4; mt++)
#pragma unroll
        for (int nt = 0; nt < 4; nt++)
#pragma unroll
            for (int i = 0; i < 4; i++) c[mt][nt][i] = 0.0f;

    const int lr = t >> 1, gx = t & 1, lk = gx * 8;
    const float* Ap = Qm + bo + (size_t)(m0 + lr) * 512 + lk;
    const float* Wp = Km + bo + (size_t)(n0 + lr) * 512 + lk;

    sts_perm(As[0], gx, lr, *(const float4*)Ap, *(const float4*)(Ap + 4));
    sts_perm(Ws[0], gx, lr, *(const float4*)Wp, *(const float4*)(Wp + 4));
    __syncthreads();

    int st = 0;
    for (int k0 = 0; k0 < 512; k0 += 16) {
        float4 na0, na1, nw0, nw1;
        const bool more = (k0 + 16) < 512;
        if (more) {
            na0 = *(const float4*)(Ap + k0 + 16);
            na1 = *(const float4*)(Ap + k0 + 20);
            nw0 = *(const float4*)(Wp + k0 + 16);
            nw1 = *(const float4*)(Wp + k0 + 20);
        }
        MMA_STAGE_P(As[st], Ws[st], c);
        if (more) {
            int ns = st ^ 1;
            sts_perm(As[ns], gx, lr, na0, na1);
            sts_perm(Ws[ns], gx, lr, nw0, nw1);
            __syncthreads();
            st = ns;
        }
    }

#pragma unroll
    for (int mt = 0; mt < 4; mt++) {
        int q0 = m0 + wm + mt * 16 + g;
        int q1 = q0 + 8;
#pragma unroll
        for (int nt = 0; nt < 4; nt++) {
            int kk = n0 + wn + nt * 8 + 2 * q;
            float2 o0, o1;
            o0.x = (kk     > q0) ? -1e30f : c[mt][nt][0] * scale;
            o0.y = (kk + 1 > q0) ? -1e30f : c[mt][nt][1] * scale;
            o1.x = (kk     > q1) ? -1e30f : c[mt][nt][2] * scale;
            o1.y = (kk + 1 > q1) ? -1e30f : c[mt][nt][3] * scale;
            *(float2*)&Cb[(size_t)q0 * 512 + kk] = o0;
            *(float2*)&Cb[(size_t)q1 * 512 + kk] = o1;
        }
    }
}

// ====== mma AV: O = attn @ V, K truncated (exact) =============================
__global__ __launch_bounds__(256) void gemm_mma_av(
    const float* __restrict__ Am, const float* __restrict__ Bm, float* __restrict__ C)
{
    __shared__ uint32_t As[2][STAGEW];
    __shared__ uint32_t Vs[2][16 * SST];
    const size_t bo = (size_t)blockIdx.z * 262144;
    const float* B = Bm + bo;
    float* Cb = C + bo;
    const int m0 = blockIdx.y * 128, n0 = blockIdx.x * 128;
    const int Kmax = m0 + 128;
    const int t = threadIdx.x, wid = t >> 5, lane = t & 31;
    const int wm = (wid >> 2) * 64, wn = (wid & 3) * 32;
    const int g = lane >> 2, q = lane & 3;

    float c[4][4][4];
#pragma unroll
    for (int mt = 0; mt < 4; mt++)
#pragma unroll
        for (int nt = 0; nt < 4; nt++)
#pragma unroll
            for (int i = 0; i < 4; i++) c[mt][nt][i] = 0.0f;

    const int lr = t >> 1, gx = t & 1, lk = gx * 8;
    const float* Ap = Am + bo + (size_t)(m0 + lr) * 512 + lk;
    const int vkr = t >> 4, vnc = (t & 15) * 8;
    const float* Vp = B + (size_t)vkr * 512 + n0 + vnc;

    {
        sts_perm(As[0], gx, lr, *(const float4*)Ap, *(const float4*)(Ap + 4));
        float4 v0 = *(const float4*)(Vp);
        float4 v1 = *(const float4*)(Vp + 4);
        uint32_t* d = &Vs[0][vkr * SST + vnc];
        d[0] = __float_as_uint(v0.x); d[1] = __float_as_uint(v0.y);
        d[2] = __float_as_uint(v0.z); d[3] = __float_as_uint(v0.w);
        d[4] = __float_as_uint(v1.x); d[5] = __float_as_uint(v1.y);
        d[6] = __float_as_uint(v1.z); d[7] = __float_as_uint(v1.w);
    }
    __syncthreads();

    int st = 0;
    for (int k0 = 0; k0 < Kmax; k0 += 16) {
        float4 na0, na1, nv0, nv1;
        const bool more = (k0 + 16) < Kmax;
        if (more) {
            na0 = *(const float4*)(Ap + k0 + 16);
            na1 = *(const float4*)(Ap + k0 + 20);
            nv0 = *(const float4*)(Vp + (size_t)(k0 + 16) * 512);
            nv1 = *(const float4*)(Vp + (size_t)(k0 + 16) * 512 + 4);
        }
        MMA_STAGE_AV(As[st], Vs[st], c);
        if (more) {
            int ns = st ^ 1;
            sts_perm(As[ns], gx, lr, na0, na1);
            uint32_t* d = &Vs[ns][vkr * SST + vnc];
            d[0] = __float_as_uint(nv0.x); d[1] = __float_as_uint(nv0.y);
            d[2] = __float_as_uint(nv0.z); d[3] = __float_as_uint(nv0.w);
            d[4] = __float_as_uint(nv1.x); d[5] = __float_as_uint(nv1.y);
            d[6] = __float_as_uint(nv1.z); d[7] = __float_as_uint(nv1.w);
            __syncthreads();
            st = ns;
        }
    }

#pragma unroll
    for (int mt = 0; mt < 4; mt++) {
        int mrow = m0 + wm + mt * 16 + g;
#pragma unroll
        for (int nt = 0; nt < 4; nt++) {
            int ncol = wn + nt * 8 + 2 * q;
            float2 o0 = make_float2(c[mt][nt][0], c[mt][nt][1]);
            float2 o1 = make_float2(c[mt][nt][2], c[mt][nt][3]);
            *(float2*)&Cb[(size_t)mrow * 512 + n0 + ncol]       = o0;
            *(float2*)&Cb[(size_t)(mrow + 8) * 512 + n0 + ncol] = o1;
        }
    }
}

// ======================= copy observed rows into lstm_hidden ==================
__global__ void copy_obs_k(const float* __restrict__ obs, float* __restrict__ LH)
{
    size_t i = (size_t)blockIdx.x * blockDim.x + threadIdx.x;
    if (i < (size_t)Bn * OBSn * Hd) {
        size_t b = i >> 17;
        size_t rem = i & 131071;
        LH[b * 262144 + rem] = obs[i];
    }
}

// ============ persistent LSTM v10: v8 + packed f32x2 GEMV =====================
// 8 warps = 2 gate-pairs x 4 k-quarters; lane covers batches (lane, lane+32).
// GEMV accumulates with fma.rn.f32x2 (2 MACs/instr): FFMA issue floor halves.
#define HSTRIDE 516
#define WSTRIDE 512
#define GPAD 66
__global__ __launch_bounds__(256, 1) void lstm_persist(
    const float* __restrict__ obs, const float* __restrict__ XG,
    const float* __restrict__ Whh, float* __restrict__ LH,
    float* __restrict__ Hb)
{
    extern __shared__ float sh[];
    float* Hs = sh;
    float* Ws = sh + 64 * HSTRIDE;
    __shared__ float gsm[4][16 * GPAD];

    const int t = threadIdx.x;
    const int ublk = blockIdx.x * 4;
    const int grp = blockIdx.x >> 4;

    for (int idx = t; idx < 16 * 128; idx += 256) {
        int row = idx >> 7, qq = idx & 127;
        int g = row >> 2, j = row & 3;
        float4 v = *(const float4*)(Whh + (size_t)(g * 512 + ublk + j) * 512 + qq * 4);
        *(float4*)(Ws + row * WSTRIDE + qq * 4) = v;
    }

    const int wid = t >> 5, lane = t & 31;
    const int gp = wid & 1, kq = wid >> 1;
    const int rbase = gp * 8;
    const int kbase = kq * 128;

    const int pb = t >> 2, pj = t & 3;
    float c_reg = obs[(size_t)pb * 131072 + 255 * 512 + ublk + pj];

    const int crow = t >> 7;
    const int ccol = (t & 127) * 4;

    for (int s = 0; s < 256; s++) {
        const float* xrow = XG + (size_t)(pb * 256 + s) * 2048 + ublk + pj;
        float xg0 = __ldcg(xrow);
        float xg1 = __ldcg(xrow + 512);
        float xg2 = __ldcg(xrow + 1024);
        float xg3 = __ldcg(xrow + 1536);

        {
            const float* hsrc; size_t hstr;
            if (s == 0) { hsrc = obs + 255 * 512; hstr = 131072; }
            else        { hsrc = Hb + (size_t)(s & 1) * (Bn * Hd); hstr = 512; }
#pragma unroll
            for (int i = 0; i < 32; i++) {
                int r = 2 * i + crow;
                float4 v = __ldcg((const float4*)(hsrc + (size_t)r * hstr + ccol));
                *(float4*)(Hs + r * HSTRIDE + ccol) = v;
            }
        }
        __syncthreads();

        // GEMV with packed f32x2 FMAs
        {
            const float* xp0 = Hs + lane * HSTRIDE + kbase;
            const float* xp1 = Hs + (lane + 32) * HSTRIDE + kbase;
            const float* wp = Ws + rbase * WSTRIDE + kbase;
            uint64_t a0[8], a1[8];
#pragma unroll
            for (int r = 0; r < 8; r++) { a0[r] = 0ull; a1[r] = 0ull; }
#pragma unroll 4
            for (int k0 = 0; k0 < 128; k0 += 4) {
                float4 x0 = *(const float4*)(xp0 + k0);
                float4 x1 = *(const float4*)(xp1 + k0);
                uint64_t x0lo, x0hi, x1lo, x1hi;
                PACK2(x0lo, x0.x, x0.y); PACK2(x0hi, x0.z, x0.w);
                PACK2(x1lo, x1.x, x1.y); PACK2(x1hi, x1.z, x1.w);
#pragma unroll
                for (int r = 0; r < 8; r++) {
                    float4 w = *(const float4*)(wp + r * WSTRIDE + k0);
                    uint64_t wlo, whi;
                    PACK2(wlo, w.x, w.y); PACK2(whi, w.z, w.w);
                    FMA2(a0[r], x0lo, wlo); FMA2(a0[r], x0hi, whi);
                    FMA2(a1[r], x1lo, wlo); FMA2(a1[r], x1hi, whi);
                }
            }
#pragma unroll
            for (int r = 0; r < 8; r++) {
                float lo, hi;
                UNPACK2(lo, hi, a0[r]);
                gsm[kq][(rbase + r) * GPAD + lane] = lo + hi;
                UNPACK2(lo, hi, a1[r]);
                gsm[kq][(rbase + r) * GPAD + lane + 32] = lo + hi;
            }
        }
        __syncthreads();

        // pointwise gate math + dual h store
        {
            int r0 = 0 * 4 + pj, r1 = 1 * 4 + pj, r2 = 2 * 4 + pj, r3 = 3 * 4 + pj;
            float gi = xg0, gf = xg1, gg = xg2, go = xg3;
#pragma unroll
            for (int kqq = 0; kqq < 4; kqq++) {
                gi += gsm[kqq][r0 * GPAD + pb];
                gf += gsm[kqq][r1 * GPAD + pb];
                gg += gsm[kqq][r2 * GPAD + pb];
                go += gsm[kqq][r3 * GPAD + pb];
            }
            c_reg = sigmoidf_(gf) * c_reg + sigmoidf_(gi) * tanhf(gg);
            float hv = sigmoidf_(go) * tanhf(c_reg);
            LH[(size_t)pb * 262144 + (size_t)(256 + s) * 512 + ublk + pj] = hv;
            Hb[(size_t)((s + 1) & 1) * (Bn * Hd) + (size_t)pb * 512 + ublk + pj] = hv;
        }

        // two-level grid barrier
        __threadfence();
        __syncthreads();
        if (t == 0) {
            unsigned snap = g_bar_gen;
            unsigned o = atomicAdd(&g_bar_grp[grp], 1u);
            if (o == 15u) {
                g_bar_grp[grp] = 0;
                __threadfence();
                unsigned r = atomicAdd(&g_bar_root, 1u);
                if (r == 7u) {
                    g_bar_root = 0;
                    __threadfence();
                    g_bar_gen = snap + 1u;
                } else {
                    while (g_bar_gen == snap) __nanosleep(32);
                }
            } else {
                while (g_bar_gen == snap) __nanosleep(32);
            }
            __threadfence();
        }
        __syncthreads();
    }
}

// ====================== fused GLU + LayerNorm =================================
__global__ __launch_bounds__(256) void gluln_k(
    const float* __restrict__ a1, const float* __restrict__ a2,
    const float* __restrict__ y1, const float* __restrict__ y2,
    const float* __restrict__ gamma, const float* __restrict__ beta,
    float* __restrict__ outp, int splitY)
{
    __shared__ float red[8];
    const int r = blockIdx.x;
    const int t = threadIdx.x;
    const float* yp;
    if (splitY) {
        int b = r >> 9, tt = r & 511;
        yp = (tt < 256) ? (y1 + ((size_t)(b * 256 + tt)) * 512)
                        : (y2 + ((size_t)(b * 256 + tt - 256)) * 512);
    } else {
        yp = y1 + (size_t)r * 512;
    }
    const float* p1 = a1 + (size_t)r * 512;
    const float* p2 = a2 + (size_t)r * 512;
    float z0 = sigmoidf_(p1[t])       * p2[t]       + yp[t];
    float z1 = sigmoidf_(p1[t + 256]) * p2[t + 256] + yp[t + 256];

    float s = z0 + z1;
#pragma unroll
    for (int o = 16; o > 0; o >>= 1) s += __shfl_xor_sync(0xffffffffu, s, o);
    if ((t & 31) == 0) red[t >> 5] = s;
    __syncthreads();
    if (t < 32) {
        float a = (t < 8) ? red[t] : 0.0f;
#pragma unroll
        for (int o = 4; o > 0; o >>= 1) a += __shfl_xor_sync(0xffffffffu, a, o);
        if (t == 0) red[0] = a;
    }
    __syncthreads();
    float mu = red[0] * (1.0f / 512.0f);
    float d0 = z0 - mu, d1 = z1 - mu;
    float s2 = d0 * d0 + d1 * d1;
    __syncthreads();
#pragma unroll
    for (int o = 16; o > 0; o >>= 1) s2 += __shfl_xor_sync(0xffffffffu, s2, o);
    if ((t & 31) == 0) red[t >> 5] = s2;
    __syncthreads();
    if (t < 32) {
        float a = (t < 8) ? red[t] : 0.0f;
#pragma unroll
        for (int o = 4; o > 0; o >>= 1) a += __shfl_xor_sync(0xffffffffu, a, o);
        if (t == 0) red[0] = a;
    }
    __syncthreads();
    float inv = rsqrtf(red[0] * (1.0f / 512.0f) + 1e-5f);
    outp[(size_t)r * 512 + t]       = gamma[t]       * d0 * inv + beta[t];
    outp[(size_t)r * 512 + t + 256] = gamma[t + 256] * d1 * inv + beta[t + 256];
}

// ====== mask-aware row softmax ================================================
__global__ __launch_bounds__(256) void softmax_k(
    const float* __restrict__ S, float* __restrict__ A)
{
    __shared__ float red[8];
    const int r = blockIdx.x;
    const int t = threadIdx.x;
    const int qpos = r & 511;
    const float* p = S + (size_t)r * 512;
    float v0 = (t <= qpos)       ? p[t]       : -3.4e38f;
    float v1 = (t + 256 <= qpos) ? p[t + 256] : -3.4e38f;
    float m = fmaxf(v0, v1);
#pragma unroll
    for (int o = 16; o > 0; o >>= 1) m = fmaxf(m, __shfl_xor_sync(0xffffffffu, m, o));
    if ((t & 31) == 0) red[t >> 5] = m;
    __syncthreads();
    if (t < 32) {
        float a = (t < 8) ? red[t] : -3.4e38f;
#pragma unroll
        for (int o = 4; o > 0; o >>= 1) a = fmaxf(a, __shfl_xor_sync(0xffffffffu, a, o));
        if (t == 0) red[0] = a;
    }
    __syncthreads();
    float mx = red[0];
    float e0 = (t <= qpos)       ? expf(v0 - mx) : 0.0f;
    float e1 = (t + 256 <= qpos) ? expf(v1 - mx) : 0.0f;
    float s = e0 + e1;
    __syncthreads();
#pragma unroll
    for (int o = 16; o > 0; o >>= 1) s += __shfl_xor_sync(0xffffffffu, s, o);
    if ((t & 31) == 0) red[t >> 5] = s;
    __syncthreads();
    if (t < 32) {
        float a = (t < 8) ? red[t] : 0.0f;
#pragma unroll
        for (int o = 4; o > 0; o >>= 1) a += __shfl_xor_sync(0xffffffffu, a, o);
        if (t == 0) red[0] = a;
    }
    __syncthreads();
    float inv = 1.0f / red[0];
    A[(size_t)r * 512 + t]       = e0 * inv;
    A[(size_t)r * 512 + t + 256] = e1 * inv;
}

// ================================= host =======================================
extern "C" void kernel_launch(void* const* d_in, const int* in_sizes, int n_in,
                              void* d_out, int out_size)
{
    const float* obs   = (const float*)d_in[0];
    const float* fut   = (const float*)d_in[1];
    const float* W_ih  = (const float*)d_in[2];
    const float* W_hh  = (const float*)d_in[3];
    const float* b_ih  = (const float*)d_in[4];
    const float* b_hh  = (const float*)d_in[5];
    const float* g1W1  = (const float*)d_in[6];
    const float* g1b1  = (const float*)d_in[7];
    const float* g1W2  = (const float*)d_in[8];
    const float* g1b2  = (const float*)d_in[9];
    const float* g1g   = (const float*)d_in[10];
    const float* g1b   = (const float*)d_in[11];
    const float* Wq    = (const float*)d_in[12];
    const float* bq    = (const float*)d_in[13];
    const float* Wk    = (const float*)d_in[14];
    const float* bk    = (const float*)d_in[15];
    const float* Wv    = (const float*)d_in[16];
    const float* bv    = (const float*)d_in[17];
    const float* Wo    = (const float*)d_in[18];
    const float* bo    = (const float*)d_in[19];
    const float* g2W1  = (const float*)d_in[20];
    const float* g2b1  = (const float*)d_in[21];
    const float* g2W2  = (const float*)d_in[22];
    const float* g2b2  = (const float*)d_in[23];
    const float* g2g   = (const float*)d_in[24];
    const float* g2b   = (const float*)d_in[25];

    float* out       = (float*)d_out;
    float* glu_delta = out;
    float* glu_phi   = out + (size_t)OUT1;
    float* attn      = out + (size_t)2 * OUT1;

    float *XG, *LH, *A1, *A2, *Qb, *Kb, *Vb, *Hb;
    cudaGetSymbolAddress((void**)&XG, d_XG);
    cudaGetSymbolAddress((void**)&LH, d_LH);
    cudaGetSymbolAddress((void**)&A1, d_A1);
    cudaGetSymbolAddress((void**)&A2, d_A2);
    cudaGetSymbolAddress((void**)&Qb, d_Qb);
    cudaGetSymbolAddress((void**)&Kb, d_Kb);
    cudaGetSymbolAddress((void**)&Vb, d_Vb);
    cudaGetSymbolAddress((void**)&Hb, d_Hbuf);

    // 1. X_gates = fut @ W_ih^T + (b_ih + b_hh)
    gemm_mma<<<dim3(G4 / 128, BF / 128), 256>>>(fut, W_ih, b_ih, b_hh, XG, BF, G4, Hd);

    // 2. lstm_hidden[:, :256, :] = vsn_observed
    copy_obs_k<<<(Bn * OBSn * Hd + 255) / 256, 256>>>(obs, LH);

    // 3. persistent LSTM over all 256 steps
    {
        const int smem = (64 * HSTRIDE + 16 * WSTRIDE) * 4;
        cudaFuncSetAttribute(lstm_persist, cudaFuncAttributeMaxDynamicSharedMemorySize, smem);
        lstm_persist<<<128, 256, smem>>>(obs, XG, W_hh, LH, Hb);
    }

    // 4. GLU-LN #1 -> glu_phi
    gemm_mma<<<dim3(4, 256), 256>>>(LH, g1W1, g1b1, nullptr, A1, BT, Hd, Hd);
    gemm_mma<<<dim3(4, 256), 256>>>(LH, g1W2, g1b2, nullptr, A2, BT, Hd, Hd);
    gluln_k<<<BT, 256>>>(A1, A2, obs, fut, g1g, g1b, glu_phi, 1);

    // 5. QKV
    gemm_mma<<<dim3(4, 256), 256>>>(glu_phi, Wq, bq, nullptr, Qb, BT, Hd, Hd);
    gemm_mma<<<dim3(4, 256), 256>>>(glu_phi, Wk, bk, nullptr, Kb, BT, Hd, Hd);
    gemm_mma<<<dim3(4, 256), 256>>>(glu_phi, Wv, bv, nullptr, Vb, BT, Hd, Hd);

    // 6. scores + mask-aware softmax -> attn
    gemm_mma_scores<<<dim3(4, 4, 64), 256>>>(Qb, Kb, XG, 0.04419417382415922f);
    softmax_k<<<BT, 256>>>(XG, attn);

    // 7. attn @ V -> Qb; projection -> Kb
    gemm_mma_av<<<dim3(4, 4, 64), 256>>>(attn, Vb, Qb);
    gemm_mma<<<dim3(4, 256), 256>>>(Qb, Wo, bo, nullptr, Kb, BT, Hd, Hd);

    // 8. GLU-LN #2 -> glu_delta
    gemm_mma<<<dim3(4, 256), 256>>>(Kb, g2W1, g2b1, nullptr, A1, BT, Hd, Hd);
    gemm_mma<<<dim3(4, 256), 256>>>(Kb, g2W2, g2b2, nullptr, A2, BT, Hd, Hd);
    gluln_k<<<BT, 256>>>(A1, A2, glu_phi, nullptr, g2g, g2b, glu_delta, 0);
}